// round 15
// baseline (speedup 1.0000x reference)
#include <cuda_runtime.h>
#include <cuda_fp16.h>
#include <math.h>

// ---------------------------------------------------------------------------
// StateModelEncoder — round 15: round-14 structure + fp16 storage for
// TAG-state hop features (pin/pk) and the conv5 gather copy of sx6.
// Accumulation stays fp32 everywhere.
// ---------------------------------------------------------------------------

#define NVn 100000
#define NSn 50000
#define EVVmax 1600000
#define ESSmax 800000
#define EHmax  800000
#define EINmax 800000
#define NDEG   (NVn + 3 * NSn)
#define ETOT   (EVVmax + ESSmax + EHmax + EINmax)
#define ZW     36
#define AST    68

// ------------------------- scratch (device globals) ------------------------
__device__ __align__(16) float g_xpad[NVn * 8];
__device__ float g_dinv_v[NVn];
__device__ __align__(16) float g_z[(size_t)NVn * ZW];
__device__ __align__(16) float g_pv[2][NVn * 8];
__device__ __align__(16) float g_WzW[4][40 * 64];
__device__ float g_c0W[4][64];
__device__ __align__(16) float g_aggw[(size_t)NSn * 36];
__device__ __align__(16) float g_aggu[(size_t)NSn * 36];
__device__ __align__(16) float g_aggin[(size_t)NSn * 36];
__device__ float g_wsum[NSn];
__device__ __align__(16) float g_ta[(size_t)NSn * 64];
__device__ __align__(16) float g_tb[(size_t)NSn * 64];
__device__ __align__(16) float g_sx5[(size_t)NSn * 64];
__device__ __align__(16) __half g_pin_h[(size_t)NSn * 64];
__device__ __align__(16) __half g_pk_h[3][(size_t)NSn * 64];
__device__ __align__(16) float g_sx6[(size_t)NSn * 64];
__device__ __align__(16) __half g_sx6h[(size_t)NSn * 64];
__device__ __align__(16) float g_accs5[(size_t)NSn * 64];
__device__ float g_dinv_s[NSn];
__device__ float g_sqd_s[NSn];
__device__ float g_cntf_s[NSn];

// unified CSR
__device__ int g_deg_all[NDEG];
__device__ int g_off_all[NDEG];
__device__ int g_cur_all[NDEG];
__device__ int g_scan_base;
__device__ int g_csr_all[ETOT];
__device__ float g_csrw[ETOT];

// ------------------ CSR count + pad + weight prep (fused) ------------------
__global__ void k_count_pad_prep(
        const int* __restrict__ ei_vv, const int* __restrict__ ei_ss,
        const int* __restrict__ ei_h,  const int* __restrict__ ei_in,
        int Evv, int Ess, int Eh, int Ein,
        const float* __restrict__ x,
        const float* __restrict__ W1_rel, const float* __restrict__ W1_root,
        const float* __restrict__ b1,
        const float* __restrict__ W12, const float* __restrict__ b12,
        const float* __restrict__ W3_rel, const float* __restrict__ W32_l,
        const float* __restrict__ W4_l,  const float* __restrict__ W42_l) {
    int t0 = blockIdx.x * blockDim.x + threadIdx.x;
    if (t0 == 0) g_scan_base = 0;

    if (t0 < NVn * 8) {
        int v = t0 >> 3, i = t0 & 7;
        float xv = (i < 5) ? x[v * 5 + i] : 0.f;
        g_xpad[t0] = xv;
        if (i < 5) g_z[(size_t)v * ZW + i] = xv;
    }
    if (t0 < 4 * 41 * 64) {
        int m = t0 / (41 * 64);
        int r = t0 % (41 * 64);
        int i = r >> 6, c = r & 63;
        const float* Wm = (m == 0) ? W3_rel : (m == 1) ? W32_l : (m == 2) ? W4_l : W42_l;
        float acc = 0.f;
        if (i < 40) {
            if (i < 35) {
#pragma unroll 8
                for (int j = 0; j < 64; j++) {
                    float wz;
                    if (i < 5)       wz = W1_root[i * 64 + j] + W12[i * 64 + j];
                    else if (i < 20) wz = W1_rel[(i - 5) * 64 + j];
                    else             wz = W12[(i - 15) * 64 + j];
                    acc += wz * Wm[j * 64 + c];
                }
                g_WzW[m][i * 64 + c] = acc;
            }
        } else {
#pragma unroll 8
            for (int j = 0; j < 64; j++) acc += (b1[j] + b12[j]) * Wm[j * 64 + c];
            g_c0W[m][c] = acc;
        }
    }

    int t = t0;
    if (t < Evv) { atomicAdd(g_deg_all + ei_vv[Evv + t], 1); return; }
    t -= Evv;
    if (t < Ess) { atomicAdd(g_deg_all + NVn + ei_ss[Ess + t], 1); return; }
    t -= Ess;
    if (t < Eh)  { atomicAdd(g_deg_all + NVn + NSn + ei_h[Eh + t], 1); return; }
    t -= Eh;
    if (t < Ein) { atomicAdd(g_deg_all + NVn + 2 * NSn + ei_in[Ein + t], 1); }
}

// one-pass scan (arrival-ordered block bases) + dinv/sqd/cnt.
__global__ void k_scan(int n) {
    __shared__ int sh[1024];
    __shared__ int s_base;
    int i = blockIdx.x * 1024 + threadIdx.x;
    int v = (i < n) ? g_deg_all[i] : 0;
    sh[threadIdx.x] = v;
    __syncthreads();
    for (int o = 1; o < 1024; o <<= 1) {
        int t = (threadIdx.x >= o) ? sh[threadIdx.x - o] : 0;
        __syncthreads();
        sh[threadIdx.x] += t;
        __syncthreads();
    }
    if (threadIdx.x == 1023) s_base = atomicAdd(&g_scan_base, sh[1023]);
    __syncthreads();
    if (i < n) {
        int o = s_base + sh[threadIdx.x] - v;
        g_off_all[i] = o;
        g_cur_all[i] = o;
        if (i < NVn) {
            g_dinv_v[i] = (v > 0) ? rsqrtf((float)v) : 0.f;
        } else if (i < NVn + NSn) {
            int s = i - NVn;
            g_dinv_s[s] = (v > 0) ? rsqrtf((float)v) : 0.f;
            g_sqd_s[s]  = sqrtf((float)v);
            g_cntf_s[s] = (float)v;
        }
    }
}

__global__ void k_fill_all(const int* __restrict__ ei_vv, const int* __restrict__ et_vv,
                           const int* __restrict__ ei_ss, const int* __restrict__ ei_h,
                           const float* __restrict__ ew_h, const int* __restrict__ ei_in,
                           int Evv, int Ess, int Eh, int Ein) {
    int t = blockIdx.x * blockDim.x + threadIdx.x;
    if (t < Evv) {
        int slot = atomicAdd(g_cur_all + ei_vv[Evv + t], 1);
        g_csr_all[slot] = ei_vv[t] | (et_vv[t] << 20);
        return;
    }
    t -= Evv;
    if (t < Ess) {
        int slot = atomicAdd(g_cur_all + NVn + ei_ss[Ess + t], 1);
        g_csr_all[slot] = ei_ss[t];
        return;
    }
    t -= Ess;
    if (t < Eh) {
        int slot = atomicAdd(g_cur_all + NVn + NSn + ei_h[Eh + t], 1);
        g_csr_all[slot] = ei_h[t];
        g_csrw[slot] = ew_h[t];
        return;
    }
    t -= Eh;
    if (t < Ein) {
        int slot = atomicAdd(g_cur_all + NVn + 2 * NSn + ei_in[Ein + t], 1);
        g_csr_all[slot] = ei_in[t];
    }
}

// --------------------------- game-graph kernels ----------------------------
__global__ void k_rgcn_hop1(float* __restrict__ p1) {
    int gt = blockIdx.x * blockDim.x + threadIdx.x;
    int w = gt >> 5, lane = gt & 31;
    if (w >= NVn) return;
    int base = g_off_all[w], deg = g_deg_all[w];
    int sub = lane >> 3, li = lane & 7;
    float a0 = 0.f, a1 = 0.f, a2 = 0.f, ah = 0.f;
    float c0 = 0.f, c1 = 0.f;
#pragma unroll 4
    for (int j = sub; j < deg; j += 4) {
        int pk = g_csr_all[base + j];
        int s = pk & 0xFFFFF, t = pk >> 20;
        float xv = g_xpad[(size_t)s * 8 + li];
        ah += g_dinv_v[s] * xv;
        if (t == 0)      { a0 += xv; c0 += 1.f; }
        else if (t == 1) { a1 += xv; c1 += 1.f; }
        else             { a2 += xv; }
    }
#pragma unroll
    for (int o = 8; o < 32; o <<= 1) {
        a0 += __shfl_xor_sync(0xffffffffu, a0, o);
        a1 += __shfl_xor_sync(0xffffffffu, a1, o);
        a2 += __shfl_xor_sync(0xffffffffu, a2, o);
        ah += __shfl_xor_sync(0xffffffffu, ah, o);
        c0 += __shfl_xor_sync(0xffffffffu, c0, o);
        c1 += __shfl_xor_sync(0xffffffffu, c1, o);
    }
    if (sub == 0) {
        float dvd = g_dinv_v[w];
        float h1 = dvd * ah;
        float c2 = (float)deg - c0 - c1;
        if (li < 5) {
            float* zz = g_z + (size_t)w * ZW;
            zz[5 + li]  = a0 / fmaxf(c0, 1.f);
            zz[10 + li] = a1 / fmaxf(c1, 1.f);
            zz[15 + li] = a2 / fmaxf(c2, 1.f);
            zz[20 + li] = h1;
            if (li == 0) zz[35] = 0.f;
        }
        p1[(size_t)w * 8 + li] = dvd * h1;
    }
}

__global__ void k_hop8_gather(const float* __restrict__ pprev, float* __restrict__ pnext,
                              int k, int write_p) {
    int gt = blockIdx.x * blockDim.x + threadIdx.x;
    int w = gt >> 5, lane = gt & 31;
    if (w >= NVn) return;
    int base = g_off_all[w], deg = g_deg_all[w];
    int pair = lane >> 1, h = lane & 1;
    float4 a = make_float4(0.f, 0.f, 0.f, 0.f);
    for (int j = pair; j < deg; j += 16) {
        int s = g_csr_all[base + j] & 0xFFFFF;
        float4 v = ((const float4*)(pprev + (size_t)s * 8))[h];
        a.x += v.x; a.y += v.y; a.z += v.z; a.w += v.w;
    }
#pragma unroll
    for (int o = 2; o < 32; o <<= 1) {
        a.x += __shfl_xor_sync(0xffffffffu, a.x, o);
        a.y += __shfl_xor_sync(0xffffffffu, a.y, o);
        a.z += __shfl_xor_sync(0xffffffffu, a.z, o);
        a.w += __shfl_xor_sync(0xffffffffu, a.w, o);
    }
    if (lane < 2) {
        float dv = g_dinv_v[w];
        float4 hx = make_float4(dv * a.x, dv * a.y, dv * a.z, dv * a.w);
        float* zz = g_z + (size_t)w * ZW + 20 + k * 5;
        if (h == 0) { zz[0] = hx.x; zz[1] = hx.y; zz[2] = hx.z; zz[3] = hx.w; }
        else        { zz[4] = hx.x; }
        if (write_p)
            ((float4*)(pnext + (size_t)w * 8))[h] =
                make_float4(dv * hx.x, dv * hx.y, dv * hx.z, dv * hx.w);
    }
}

// --------- ei_h / ei_in z-gathers (one warp per node per graph) ------------
__global__ void k_gather_hin() {
    int gt = blockIdx.x * blockDim.x + threadIdx.x;
    int w2 = gt >> 5, lane = gt & 31;
    if (w2 >= 2 * NSn) return;
    int sub = lane >> 4, li = lane & 15;
    int isH = (w2 < NSn);
    int w = isH ? w2 : (w2 - NSn);

    if (isH) {
        int base = g_off_all[NVn + NSn + w], deg = g_deg_all[NVn + NSn + w];
        float4 aW = make_float4(0.f, 0.f, 0.f, 0.f);
        float4 aU = make_float4(0.f, 0.f, 0.f, 0.f);
        float wsum = 0.f;
        for (int j0 = 0; j0 < deg; j0 += 32) {
            int idx = j0 + lane;
            int sl = 0; float wl = 0.f;
            if (idx < deg) { sl = g_csr_all[base + idx]; wl = g_csrw[base + idx]; }
            wsum += wl;
            int mres = deg - j0; if (mres > 32) mres = 32;
#pragma unroll
            for (int jj = 0; jj < 16; jj++) {
                int e2 = 2 * jj + sub;
                int s = __shfl_sync(0xffffffffu, sl, e2);
                float wt = __shfl_sync(0xffffffffu, wl, e2);
                if (e2 < mres && li < 9) {
                    float4 t = ((const float4*)(g_z + (size_t)s * ZW))[li];
                    aU.x += t.x; aU.y += t.y; aU.z += t.z; aU.w += t.w;
                    aW.x += wt * t.x; aW.y += wt * t.y; aW.z += wt * t.z; aW.w += wt * t.w;
                }
            }
        }
        aU.x += __shfl_xor_sync(0xffffffffu, aU.x, 16);
        aU.y += __shfl_xor_sync(0xffffffffu, aU.y, 16);
        aU.z += __shfl_xor_sync(0xffffffffu, aU.z, 16);
        aU.w += __shfl_xor_sync(0xffffffffu, aU.w, 16);
        aW.x += __shfl_xor_sync(0xffffffffu, aW.x, 16);
        aW.y += __shfl_xor_sync(0xffffffffu, aW.y, 16);
        aW.z += __shfl_xor_sync(0xffffffffu, aW.z, 16);
        aW.w += __shfl_xor_sync(0xffffffffu, aW.w, 16);
#pragma unroll
        for (int o = 16; o; o >>= 1) wsum += __shfl_xor_sync(0xffffffffu, wsum, o);
        if (sub == 0 && li < 9) {
            ((float4*)(g_aggu + (size_t)w * 36))[li] = aU;
            ((float4*)(g_aggw + (size_t)w * 36))[li] = aW;
        }
        if (lane == 0) g_wsum[w] = wsum;
    } else {
        int base = g_off_all[NVn + 2 * NSn + w], deg = g_deg_all[NVn + 2 * NSn + w];
        float4 aU = make_float4(0.f, 0.f, 0.f, 0.f);
        for (int j0 = 0; j0 < deg; j0 += 32) {
            int idx = j0 + lane;
            int sl = (idx < deg) ? g_csr_all[base + idx] : 0;
            int mres = deg - j0; if (mres > 32) mres = 32;
#pragma unroll
            for (int jj = 0; jj < 16; jj++) {
                int e2 = 2 * jj + sub;
                int s = __shfl_sync(0xffffffffu, sl, e2);
                if (e2 < mres && li < 9) {
                    float4 t = ((const float4*)(g_z + (size_t)s * ZW))[li];
                    aU.x += t.x; aU.y += t.y; aU.z += t.z; aU.w += t.w;
                }
            }
        }
        aU.x += __shfl_xor_sync(0xffffffffu, aU.x, 16);
        aU.y += __shfl_xor_sync(0xffffffffu, aU.y, 16);
        aU.z += __shfl_xor_sync(0xffffffffu, aU.z, 16);
        aU.w += __shfl_xor_sync(0xffffffffu, aU.w, 16);
        if (sub == 0 && li < 9)
            ((float4*)(g_aggin + (size_t)w * 36))[li] = aU;
    }
}

// ---------------------- tiled GEMM building blocks -------------------------
__device__ __forceinline__ void stage_w(float* sW, const float* __restrict__ g, int n) {
    for (int e = threadIdx.x; e < n; e += 256) sW[e] = g[e];
}
__device__ __forceinline__ void stage_a64(float* sA, const float* __restrict__ g,
                                          int vbase, const float* sScale) {
    for (int e = threadIdx.x; e < 64 * 64; e += 256) {
        int n = e >> 6, j = e & 63;
        int v = vbase + n; if (v >= NSn) v = NSn - 1;
        float s = sScale ? sScale[n] : 1.f;
        sA[j * AST + n] = g[(size_t)v * 64 + j] * s;
    }
}
// half-source variant
__device__ __forceinline__ void stage_a64h(float* sA, const __half* __restrict__ g,
                                           int vbase, const float* sScale) {
    for (int e = threadIdx.x; e < 64 * 64; e += 256) {
        int n = e >> 6, j = e & 63;
        int v = vbase + n; if (v >= NSn) v = NSn - 1;
        float s = sScale ? sScale[n] : 1.f;
        sA[j * AST + n] = __half2float(g[(size_t)v * 64 + j]) * s;
    }
}
__device__ __forceinline__ void stage_a36(float* sA, const float* __restrict__ g,
                                          int vbase, const float* sScale) {
    for (int e = threadIdx.x; e < 64 * 36; e += 256) {
        int n = e / 36, j = e - n * 36;
        int v = vbase + n; if (v >= NSn) v = NSn - 1;
        float s = sScale ? sScale[n] : 1.f;
        sA[j * AST + n] = g[(size_t)v * 36 + j] * s;
    }
}
__device__ __forceinline__ void gemm16(const float* __restrict__ sW, const float* __restrict__ sA,
                                       int J, int c4, int n0, float acc[4][4]) {
#pragma unroll 4
    for (int j = 0; j < J; j++) {
        float4 wv = *(const float4*)(sW + j * 64 + c4);
        float4 av = *(const float4*)(sA + j * AST + n0);
        acc[0][0] += av.x * wv.x; acc[0][1] += av.x * wv.y; acc[0][2] += av.x * wv.z; acc[0][3] += av.x * wv.w;
        acc[1][0] += av.y * wv.x; acc[1][1] += av.y * wv.y; acc[1][2] += av.y * wv.z; acc[1][3] += av.y * wv.w;
        acc[2][0] += av.z * wv.x; acc[2][1] += av.z * wv.y; acc[2][2] += av.z * wv.z; acc[2][3] += av.z * wv.w;
        acc[3][0] += av.w * wv.x; acc[3][1] += av.w * wv.y; acc[3][2] += av.w * wv.z; acc[3][3] += av.w * wv.w;
    }
}
__device__ __forceinline__ void pack_h4(__half* dst, float4 o) {
    __half2 q0 = __floats2half2_rn(o.x, o.y);
    __half2 q1 = __floats2half2_rn(o.z, o.w);
    uint2 st;
    st.x = *reinterpret_cast<unsigned*>(&q0);
    st.y = *reinterpret_cast<unsigned*>(&q1);
    *reinterpret_cast<uint2*>(dst) = st;
}

// --------------------- state dense chain (layers 2-5) ----------------------
__global__ void __launch_bounds__(256) k_state_dense(
        const float* __restrict__ state_x, const float* __restrict__ W3_root,
        const float* __restrict__ b3, const float* __restrict__ W32_r,
        const float* __restrict__ b32, const float* __restrict__ W4_r,
        const float* __restrict__ b4, const float* __restrict__ W42_r,
        const float* __restrict__ b42) {
    __shared__ float sW[64 * 64];
    __shared__ float sA[64 * AST];
    __shared__ float sInvH[64], sInvI[64], sWsum[64], sPosH[64], sPosI[64], sDin[64];
    int tid = threadIdx.x;
    int vbase = blockIdx.x * 64;
    if (tid < 64) {
        int v = vbase + tid; if (v >= NSn) v = NSn - 1;
        float ch = (float)g_deg_all[NVn + NSn + v];
        float ci = (float)g_deg_all[NVn + 2 * NSn + v];
        sInvH[tid] = 1.f / fmaxf(ch, 1.f);
        sInvI[tid] = 1.f / fmaxf(ci, 1.f);
        sPosH[tid] = (ch > 0.f) ? 1.f : 0.f;
        sPosI[tid] = (ci > 0.f) ? 1.f : 0.f;
        sWsum[tid] = g_wsum[v];
        sDin[tid]  = g_dinv_s[v];
    }
    __syncthreads();
    int c4 = (tid & 15) * 4, n0 = (tid >> 4) * 4;
    float acc[4][4];
    float4 bv, cv;

    // ---- L2: graph_conv ----
    stage_a36(sA, g_aggw, vbase, nullptr);
    stage_w(sW, g_WzW[0], 35 * 64);
    __syncthreads();
    bv = *(const float4*)(b3 + c4);
    cv = *(const float4*)(g_c0W[0] + c4);
#pragma unroll
    for (int i = 0; i < 4; i++) {
        float ws = sWsum[n0 + i];
        acc[i][0] = bv.x + ws * cv.x; acc[i][1] = bv.y + ws * cv.y;
        acc[i][2] = bv.z + ws * cv.z; acc[i][3] = bv.w + ws * cv.w;
    }
    gemm16(sW, sA, 35, c4, n0, acc);
    __syncthreads();
    for (int e = tid; e < 64 * 5; e += 256) {
        int n = e / 5, j = e - n * 5;
        int v = vbase + n; if (v >= NSn) v = NSn - 1;
        sA[j * AST + n] = state_x[(size_t)v * 5 + j];
    }
    stage_w(sW, W3_root, 5 * 64);
    __syncthreads();
    gemm16(sW, sA, 5, c4, n0, acc);
#pragma unroll
    for (int i = 0; i < 4; i++) {
        int v = vbase + n0 + i;
        if (v < NSn) {
            float4 o = make_float4(fmaxf(acc[i][0], 0.f), fmaxf(acc[i][1], 0.f),
                                   fmaxf(acc[i][2], 0.f), fmaxf(acc[i][3], 0.f));
            *(float4*)(g_ta + (size_t)v * 64 + c4) = o;
        }
    }
    __syncthreads();

    // ---- L3: conv32 ----
    stage_a36(sA, g_aggu, vbase, sInvH);
    stage_w(sW, g_WzW[1], 35 * 64);
    __syncthreads();
    bv = *(const float4*)(b32 + c4);
    cv = *(const float4*)(g_c0W[1] + c4);
#pragma unroll
    for (int i = 0; i < 4; i++) {
        float p = sPosH[n0 + i];
        acc[i][0] = bv.x + p * cv.x; acc[i][1] = bv.y + p * cv.y;
        acc[i][2] = bv.z + p * cv.z; acc[i][3] = bv.w + p * cv.w;
    }
    gemm16(sW, sA, 35, c4, n0, acc);
    __syncthreads();
    stage_a64(sA, g_ta, vbase, nullptr);
    stage_w(sW, W32_r, 64 * 64);
    __syncthreads();
    gemm16(sW, sA, 64, c4, n0, acc);
#pragma unroll
    for (int i = 0; i < 4; i++) {
        int v = vbase + n0 + i;
        if (v < NSn) {
            float4 o = make_float4(fmaxf(acc[i][0], 0.f), fmaxf(acc[i][1], 0.f),
                                   fmaxf(acc[i][2], 0.f), fmaxf(acc[i][3], 0.f));
            *(float4*)(g_tb + (size_t)v * 64 + c4) = o;
        }
    }
    __syncthreads();

    // ---- L4: conv4 ----
    stage_a36(sA, g_aggin, vbase, sInvI);
    stage_w(sW, g_WzW[2], 35 * 64);
    __syncthreads();
    bv = *(const float4*)(b4 + c4);
    cv = *(const float4*)(g_c0W[2] + c4);
#pragma unroll
    for (int i = 0; i < 4; i++) {
        float p = sPosI[n0 + i];
        acc[i][0] = bv.x + p * cv.x; acc[i][1] = bv.y + p * cv.y;
        acc[i][2] = bv.z + p * cv.z; acc[i][3] = bv.w + p * cv.w;
    }
    gemm16(sW, sA, 35, c4, n0, acc);
    __syncthreads();
    stage_a64(sA, g_tb, vbase, nullptr);
    stage_w(sW, W4_r, 64 * 64);
    __syncthreads();
    gemm16(sW, sA, 64, c4, n0, acc);
#pragma unroll
    for (int i = 0; i < 4; i++) {
        int v = vbase + n0 + i;
        if (v < NSn) {
            float4 o = make_float4(fmaxf(acc[i][0], 0.f), fmaxf(acc[i][1], 0.f),
                                   fmaxf(acc[i][2], 0.f), fmaxf(acc[i][3], 0.f));
            *(float4*)(g_ta + (size_t)v * 64 + c4) = o;
        }
    }
    __syncthreads();

    // ---- L5: conv42 -> sx5, pin(half) ----
    stage_a36(sA, g_aggin, vbase, sInvI);
    stage_w(sW, g_WzW[3], 35 * 64);
    __syncthreads();
    bv = *(const float4*)(b42 + c4);
    cv = *(const float4*)(g_c0W[3] + c4);
#pragma unroll
    for (int i = 0; i < 4; i++) {
        float p = sPosI[n0 + i];
        acc[i][0] = bv.x + p * cv.x; acc[i][1] = bv.y + p * cv.y;
        acc[i][2] = bv.z + p * cv.z; acc[i][3] = bv.w + p * cv.w;
    }
    gemm16(sW, sA, 35, c4, n0, acc);
    __syncthreads();
    stage_a64(sA, g_ta, vbase, nullptr);
    stage_w(sW, W42_r, 64 * 64);
    __syncthreads();
    gemm16(sW, sA, 64, c4, n0, acc);
#pragma unroll
    for (int i = 0; i < 4; i++) {
        int v = vbase + n0 + i;
        if (v < NSn) {
            float dv = sDin[n0 + i];
            float4 o = make_float4(fmaxf(acc[i][0], 0.f), fmaxf(acc[i][1], 0.f),
                                   fmaxf(acc[i][2], 0.f), fmaxf(acc[i][3], 0.f));
            *(float4*)(g_sx5 + (size_t)v * 64 + c4) = o;
            pack_h4(g_pin_h + (size_t)v * 64 + c4,
                    make_float4(dv * o.x, dv * o.y, dv * o.z, dv * o.w));
        }
    }
}

// TAG-state hop, p-form, fp16 storage: p_next = dinv^2 * sum(p_prev[src]).
__global__ void k_hop64ph(const __half* __restrict__ pprev, __half* __restrict__ pnext) {
    int gt = blockIdx.x * blockDim.x + threadIdx.x;
    int w = gt >> 5, lane = gt & 31;
    if (w >= NSn) return;
    int base = g_off_all[NVn + w], deg = g_deg_all[NVn + w];
    int sub = lane >> 4, li = lane & 15;
    float4 a = make_float4(0.f, 0.f, 0.f, 0.f);
    for (int j0 = 0; j0 < deg; j0 += 32) {
        int idx = j0 + lane;
        int sl = (idx < deg) ? g_csr_all[base + idx] : 0;
        int mres = deg - j0; if (mres > 32) mres = 32;
#pragma unroll
        for (int jj = 0; jj < 16; jj++) {
            int e2 = 2 * jj + sub;
            int s = __shfl_sync(0xffffffffu, sl, e2);
            if (e2 < mres) {
                uint2 u = ((const uint2*)(pprev + (size_t)s * 64))[li];
                __half2 h0 = *reinterpret_cast<__half2*>(&u.x);
                __half2 h1 = *reinterpret_cast<__half2*>(&u.y);
                float2 f0 = __half22float2(h0);
                float2 f1 = __half22float2(h1);
                a.x += f0.x; a.y += f0.y; a.z += f1.x; a.w += f1.y;
            }
        }
    }
    a.x += __shfl_xor_sync(0xffffffffu, a.x, 16);
    a.y += __shfl_xor_sync(0xffffffffu, a.y, 16);
    a.z += __shfl_xor_sync(0xffffffffu, a.z, 16);
    a.w += __shfl_xor_sync(0xffffffffu, a.w, 16);
    if (sub == 0) {
        float dv = g_dinv_s[w];
        float dv2 = dv * dv;
        pack_h4(pnext + (size_t)w * 64 + li * 4,
                make_float4(dv2 * a.x, dv2 * a.y, dv2 * a.z, dv2 * a.w));
    }
}

// conv5 sum gather over ei_ss (fp16 feature rows, fp32 accumulate/output).
__global__ void k_sum64_gather_h(const __half* __restrict__ feat, float* __restrict__ acc) {
    int gt = blockIdx.x * blockDim.x + threadIdx.x;
    int w = gt >> 5, lane = gt & 31;
    if (w >= NSn) return;
    int base = g_off_all[NVn + w], deg = g_deg_all[NVn + w];
    int sub = lane >> 4, li = lane & 15;
    float4 a = make_float4(0.f, 0.f, 0.f, 0.f);
    for (int j0 = 0; j0 < deg; j0 += 32) {
        int idx = j0 + lane;
        int sl = (idx < deg) ? g_csr_all[base + idx] : 0;
        int mres = deg - j0; if (mres > 32) mres = 32;
#pragma unroll
        for (int jj = 0; jj < 16; jj++) {
            int e2 = 2 * jj + sub;
            int s = __shfl_sync(0xffffffffu, sl, e2);
            if (e2 < mres) {
                uint2 u = ((const uint2*)(feat + (size_t)s * 64))[li];
                __half2 h0 = *reinterpret_cast<__half2*>(&u.x);
                __half2 h1 = *reinterpret_cast<__half2*>(&u.y);
                float2 f0 = __half22float2(h0);
                float2 f1 = __half22float2(h1);
                a.x += f0.x; a.y += f0.y; a.z += f1.x; a.w += f1.y;
            }
        }
    }
    a.x += __shfl_xor_sync(0xffffffffu, a.x, 16);
    a.y += __shfl_xor_sync(0xffffffffu, a.y, 16);
    a.z += __shfl_xor_sync(0xffffffffu, a.z, 16);
    a.w += __shfl_xor_sync(0xffffffffu, a.w, 16);
    if (sub == 0)
        ((float4*)(acc + (size_t)w * 64))[li] = a;
}

// TAG output dense: sx6 = relu(b2 + sx5@W2_0 + sum_k (sqd*pk_k)@W2_{k+1})
__global__ void __launch_bounds__(256) k_tag_dense(
        const float* __restrict__ W2, const float* __restrict__ b2) {
    __shared__ float sW[64 * 64];
    __shared__ float sA[64 * AST];
    __shared__ float sSq[64];
    int tid = threadIdx.x;
    int vbase = blockIdx.x * 64;
    if (tid < 64) {
        int v = vbase + tid; if (v >= NSn) v = NSn - 1;
        sSq[tid] = g_sqd_s[v];
    }
    __syncthreads();
    int c4 = (tid & 15) * 4, n0 = (tid >> 4) * 4;
    float acc[4][4];
    float4 bv;

    stage_a64(sA, g_sx5, vbase, nullptr);
    stage_w(sW, W2, 64 * 64);
    __syncthreads();
    bv = *(const float4*)(b2 + c4);
#pragma unroll
    for (int i = 0; i < 4; i++) {
        acc[i][0] = bv.x; acc[i][1] = bv.y; acc[i][2] = bv.z; acc[i][3] = bv.w;
    }
    gemm16(sW, sA, 64, c4, n0, acc);
    __syncthreads();
#pragma unroll
    for (int k = 0; k < 3; k++) {
        stage_a64h(sA, g_pk_h[k], vbase, sSq);
        stage_w(sW, W2 + (size_t)(k + 1) * 4096, 64 * 64);
        __syncthreads();
        gemm16(sW, sA, 64, c4, n0, acc);
        __syncthreads();
    }
#pragma unroll
    for (int i = 0; i < 4; i++) {
        int v = vbase + n0 + i;
        if (v < NSn) {
            float4 o = make_float4(fmaxf(acc[i][0], 0.f), fmaxf(acc[i][1], 0.f),
                                   fmaxf(acc[i][2], 0.f), fmaxf(acc[i][3], 0.f));
            *(float4*)(g_sx6 + (size_t)v * 64 + c4) = o;
            pack_h4(g_sx6h + (size_t)v * 64 + c4, o);
        }
    }
}

// conv5 dense + head.
__global__ void __launch_bounds__(256) k_conv5_head(
        const float* __restrict__ W5_l, const float* __restrict__ W5_r,
        const float* __restrict__ b5, const float* __restrict__ Wl,
        const float* __restrict__ bl, float* __restrict__ out) {
    __shared__ float sW[64 * 64];
    __shared__ float sA[64 * AST];
    __shared__ float sInv[64];
    int tid = threadIdx.x;
    int vbase = blockIdx.x * 64;
    if (tid < 64) {
        int v = vbase + tid; if (v >= NSn) v = NSn - 1;
        sInv[tid] = 1.f / fmaxf(g_cntf_s[v], 1.f);
    }
    __syncthreads();
    int c4 = (tid & 15) * 4, n0 = (tid >> 4) * 4;
    float acc[4][4];
    float4 bv;

    stage_a64(sA, g_accs5, vbase, sInv);
    stage_w(sW, W5_l, 64 * 64);
    __syncthreads();
    bv = *(const float4*)(b5 + c4);
#pragma unroll
    for (int i = 0; i < 4; i++) {
        acc[i][0] = bv.x; acc[i][1] = bv.y; acc[i][2] = bv.z; acc[i][3] = bv.w;
    }
    gemm16(sW, sA, 64, c4, n0, acc);
    __syncthreads();
    stage_a64(sA, g_sx6, vbase, nullptr);
    stage_w(sW, W5_r, 64 * 64);
    __syncthreads();
    gemm16(sW, sA, 64, c4, n0, acc);
    __syncthreads();
#pragma unroll
    for (int i = 0; i < 4; i++) {
#pragma unroll
        for (int k = 0; k < 4; k++)
            sA[(c4 + k) * AST + n0 + i] = fmaxf(acc[i][k], 0.f);
    }
    stage_w(sW, Wl, 64 * 8);
    __syncthreads();
#pragma unroll
    for (int u = 0; u < 2; u++) {
        int idx = tid * 2 + u;
        int n = idx >> 3, o = idx & 7;
        float s = bl[o];
#pragma unroll 8
        for (int j = 0; j < 64; j++) s += sA[j * AST + n] * sW[j * 8 + o];
        int v = vbase + n;
        if (v < NSn) out[(size_t)v * 8 + o] = s;
    }
}

// ------------------------------- launch ------------------------------------

extern "C" void kernel_launch(void* const* d_in, const int* in_sizes, int n_in,
                              void* d_out, int out_size) {
    const float* game_x  = (const float*)d_in[0];
    const float* state_x = (const float*)d_in[1];
    const int*   ei_vv   = (const int*)d_in[2];
    const int*   et_vv   = (const int*)d_in[3];
    const int*   ei_h    = (const int*)d_in[4];
    const float* ew_h    = (const float*)d_in[5];
    const int*   ei_in   = (const int*)d_in[6];
    const int*   ei_ss   = (const int*)d_in[7];
    const float* W1_rel  = (const float*)d_in[8];
    const float* W1_root = (const float*)d_in[9];
    const float* b1      = (const float*)d_in[10];
    const float* W12     = (const float*)d_in[11];
    const float* b12     = (const float*)d_in[12];
    const float* W2      = (const float*)d_in[13];
    const float* b2      = (const float*)d_in[14];
    const float* W3_rel  = (const float*)d_in[15];
    const float* W3_root = (const float*)d_in[16];
    const float* b3      = (const float*)d_in[17];
    const float* W32_l   = (const float*)d_in[18];
    const float* W32_r   = (const float*)d_in[19];
    const float* b32     = (const float*)d_in[20];
    const float* W4_l    = (const float*)d_in[21];
    const float* W4_r    = (const float*)d_in[22];
    const float* b4      = (const float*)d_in[23];
    const float* W42_l   = (const float*)d_in[24];
    const float* W42_r   = (const float*)d_in[25];
    const float* b42     = (const float*)d_in[26];
    const float* W5_l    = (const float*)d_in[27];
    const float* W5_r    = (const float*)d_in[28];
    const float* b5      = (const float*)d_in[29];
    const float* Wl      = (const float*)d_in[30];
    const float* bl      = (const float*)d_in[31];
    float* out = (float*)d_out;

    int Evv = in_sizes[2] / 2;
    int Eh  = in_sizes[4] / 2;
    int Ein = in_sizes[6] / 2;
    int Ess = in_sizes[7] / 2;
    int Etot = Evv + Ess + Eh + Ein;

    int* pi_deg;
    float *p_pv, *p_accs5;
    __half *p_pinh, *p_pkh, *p_sx6h;
    cudaGetSymbolAddress((void**)&pi_deg,  g_deg_all);
    cudaGetSymbolAddress((void**)&p_pv,    g_pv);
    cudaGetSymbolAddress((void**)&p_pinh,  g_pin_h);
    cudaGetSymbolAddress((void**)&p_pkh,   g_pk_h);
    cudaGetSymbolAddress((void**)&p_sx6h,  g_sx6h);
    cudaGetSymbolAddress((void**)&p_accs5, g_accs5);

    float* p_pv0 = p_pv;
    float* p_pv1 = p_pv + (size_t)NVn * 8;
    __half* p_pk0 = p_pkh;
    __half* p_pk1 = p_pkh + (size_t)NSn * 64;
    __half* p_pk2 = p_pk1 + (size_t)NSn * 64;

    const int T = 256;
    auto nb = [](long n, int t) { return (int)((n + t - 1) / t); };
    int nbv_warp = nb((long)NVn * 32, T);
    int nbs_warp = nb((long)NSn * 32, T);
    int ndense = nb(NSn, 64);

    // 0) zero unified degree array
    cudaMemsetAsync(pi_deg, 0, (size_t)NDEG * 4, 0);

    // 1) fused count + pad + weight prep, then scan, then fill
    k_count_pad_prep<<<nb(Etot, T), T>>>(ei_vv, ei_ss, ei_h, ei_in,
                                         Evv, Ess, Eh, Ein,
                                         game_x, W1_rel, W1_root, b1, W12, b12,
                                         W3_rel, W32_l, W4_l, W42_l);
    k_scan<<<nb(NDEG, 1024), 1024>>>(NDEG);
    k_fill_all<<<nb(Etot, T), T>>>(ei_vv, et_vv, ei_ss, ei_h, ew_h, ei_in,
                                   Evv, Ess, Eh, Ein);

    // 2) game graph -> z
    k_rgcn_hop1<<<nbv_warp, T>>>(p_pv0);
    k_hop8_gather<<<nbv_warp, T>>>(p_pv0, p_pv1, 1, 1);
    k_hop8_gather<<<nbv_warp, T>>>(p_pv1, p_pv0, 2, 0);

    // 3) ei_h + ei_in gathers (split), then state dense chain
    k_gather_hin<<<nb((long)2 * NSn * 32, T), T>>>();
    k_state_dense<<<ndense, 256>>>(state_x, W3_root, b3, W32_r, b32,
                                   W4_r, b4, W42_r, b42);

    // 4) TAG-state hops (fp16 storage) + dense output
    k_hop64ph<<<nbs_warp, T>>>(p_pinh, p_pk0);
    k_hop64ph<<<nbs_warp, T>>>(p_pk0, p_pk1);
    k_hop64ph<<<nbs_warp, T>>>(p_pk1, p_pk2);
    k_tag_dense<<<ndense, 256>>>(W2, b2);

    // 5) conv5 gather (fp16 rows) + dense + head
    k_sum64_gather_h<<<nbs_warp, T>>>(p_sx6h, p_accs5);
    k_conv5_head<<<ndense, 256>>>(W5_l, W5_r, b5, Wl, bl, out);
}

// round 16
// speedup vs baseline: 1.0271x; 1.0271x over previous
#include <cuda_runtime.h>
#include <math.h>

// ---------------------------------------------------------------------------
// StateModelEncoder — round 16: revert to the round-14 configuration (best
// verified: 575.6us, rel_err 3.5e-7). fp32 everywhere; unified CSR; all
// gathers; tiled-GEMM dense phases. 15 launches.
// ---------------------------------------------------------------------------

#define NVn 100000
#define NSn 50000
#define EVVmax 1600000
#define ESSmax 800000
#define EHmax  800000
#define EINmax 800000
#define NDEG   (NVn + 3 * NSn)
#define ETOT   (EVVmax + ESSmax + EHmax + EINmax)
#define ZW     36
#define AST    68

// ------------------------- scratch (device globals) ------------------------
__device__ __align__(16) float g_xpad[NVn * 8];
__device__ float g_dinv_v[NVn];
__device__ __align__(16) float g_z[(size_t)NVn * ZW];
__device__ __align__(16) float g_pv[2][NVn * 8];
__device__ __align__(16) float g_WzW[4][40 * 64];
__device__ float g_c0W[4][64];
__device__ __align__(16) float g_aggw[(size_t)NSn * 36];
__device__ __align__(16) float g_aggu[(size_t)NSn * 36];
__device__ __align__(16) float g_aggin[(size_t)NSn * 36];
__device__ float g_wsum[NSn];
__device__ __align__(16) float g_ta[(size_t)NSn * 64];
__device__ __align__(16) float g_tb[(size_t)NSn * 64];
__device__ __align__(16) float g_sx5[(size_t)NSn * 64];
__device__ __align__(16) float g_pin[(size_t)NSn * 64];
__device__ __align__(16) float g_pk[3][(size_t)NSn * 64];
__device__ __align__(16) float g_sx6[(size_t)NSn * 64];
__device__ __align__(16) float g_accs5[(size_t)NSn * 64];
__device__ float g_dinv_s[NSn];
__device__ float g_sqd_s[NSn];
__device__ float g_cntf_s[NSn];

// unified CSR
__device__ int g_deg_all[NDEG];
__device__ int g_off_all[NDEG];
__device__ int g_cur_all[NDEG];
__device__ int g_scan_base;
__device__ int g_csr_all[ETOT];
__device__ float g_csrw[ETOT];

// ------------------ CSR count + pad + weight prep (fused) ------------------
__global__ void k_count_pad_prep(
        const int* __restrict__ ei_vv, const int* __restrict__ ei_ss,
        const int* __restrict__ ei_h,  const int* __restrict__ ei_in,
        int Evv, int Ess, int Eh, int Ein,
        const float* __restrict__ x,
        const float* __restrict__ W1_rel, const float* __restrict__ W1_root,
        const float* __restrict__ b1,
        const float* __restrict__ W12, const float* __restrict__ b12,
        const float* __restrict__ W3_rel, const float* __restrict__ W32_l,
        const float* __restrict__ W4_l,  const float* __restrict__ W42_l) {
    int t0 = blockIdx.x * blockDim.x + threadIdx.x;
    if (t0 == 0) g_scan_base = 0;

    if (t0 < NVn * 8) {
        int v = t0 >> 3, i = t0 & 7;
        float xv = (i < 5) ? x[v * 5 + i] : 0.f;
        g_xpad[t0] = xv;
        if (i < 5) g_z[(size_t)v * ZW + i] = xv;
    }
    if (t0 < 4 * 41 * 64) {
        int m = t0 / (41 * 64);
        int r = t0 % (41 * 64);
        int i = r >> 6, c = r & 63;
        const float* Wm = (m == 0) ? W3_rel : (m == 1) ? W32_l : (m == 2) ? W4_l : W42_l;
        float acc = 0.f;
        if (i < 40) {
            if (i < 35) {
#pragma unroll 8
                for (int j = 0; j < 64; j++) {
                    float wz;
                    if (i < 5)       wz = W1_root[i * 64 + j] + W12[i * 64 + j];
                    else if (i < 20) wz = W1_rel[(i - 5) * 64 + j];
                    else             wz = W12[(i - 15) * 64 + j];
                    acc += wz * Wm[j * 64 + c];
                }
                g_WzW[m][i * 64 + c] = acc;
            }
        } else {
#pragma unroll 8
            for (int j = 0; j < 64; j++) acc += (b1[j] + b12[j]) * Wm[j * 64 + c];
            g_c0W[m][c] = acc;
        }
    }

    int t = t0;
    if (t < Evv) { atomicAdd(g_deg_all + ei_vv[Evv + t], 1); return; }
    t -= Evv;
    if (t < Ess) { atomicAdd(g_deg_all + NVn + ei_ss[Ess + t], 1); return; }
    t -= Ess;
    if (t < Eh)  { atomicAdd(g_deg_all + NVn + NSn + ei_h[Eh + t], 1); return; }
    t -= Eh;
    if (t < Ein) { atomicAdd(g_deg_all + NVn + 2 * NSn + ei_in[Ein + t], 1); }
}

// one-pass scan (arrival-ordered block bases) + dinv/sqd/cnt.
__global__ void k_scan(int n) {
    __shared__ int sh[1024];
    __shared__ int s_base;
    int i = blockIdx.x * 1024 + threadIdx.x;
    int v = (i < n) ? g_deg_all[i] : 0;
    sh[threadIdx.x] = v;
    __syncthreads();
    for (int o = 1; o < 1024; o <<= 1) {
        int t = (threadIdx.x >= o) ? sh[threadIdx.x - o] : 0;
        __syncthreads();
        sh[threadIdx.x] += t;
        __syncthreads();
    }
    if (threadIdx.x == 1023) s_base = atomicAdd(&g_scan_base, sh[1023]);
    __syncthreads();
    if (i < n) {
        int o = s_base + sh[threadIdx.x] - v;
        g_off_all[i] = o;
        g_cur_all[i] = o;
        if (i < NVn) {
            g_dinv_v[i] = (v > 0) ? rsqrtf((float)v) : 0.f;
        } else if (i < NVn + NSn) {
            int s = i - NVn;
            g_dinv_s[s] = (v > 0) ? rsqrtf((float)v) : 0.f;
            g_sqd_s[s]  = sqrtf((float)v);
            g_cntf_s[s] = (float)v;
        }
    }
}

__global__ void k_fill_all(const int* __restrict__ ei_vv, const int* __restrict__ et_vv,
                           const int* __restrict__ ei_ss, const int* __restrict__ ei_h,
                           const float* __restrict__ ew_h, const int* __restrict__ ei_in,
                           int Evv, int Ess, int Eh, int Ein) {
    int t = blockIdx.x * blockDim.x + threadIdx.x;
    if (t < Evv) {
        int slot = atomicAdd(g_cur_all + ei_vv[Evv + t], 1);
        g_csr_all[slot] = ei_vv[t] | (et_vv[t] << 20);
        return;
    }
    t -= Evv;
    if (t < Ess) {
        int slot = atomicAdd(g_cur_all + NVn + ei_ss[Ess + t], 1);
        g_csr_all[slot] = ei_ss[t];
        return;
    }
    t -= Ess;
    if (t < Eh) {
        int slot = atomicAdd(g_cur_all + NVn + NSn + ei_h[Eh + t], 1);
        g_csr_all[slot] = ei_h[t];
        g_csrw[slot] = ew_h[t];
        return;
    }
    t -= Eh;
    if (t < Ein) {
        int slot = atomicAdd(g_cur_all + NVn + 2 * NSn + ei_in[Ein + t], 1);
        g_csr_all[slot] = ei_in[t];
    }
}

// --------------------------- game-graph kernels ----------------------------
__global__ void k_rgcn_hop1(float* __restrict__ p1) {
    int gt = blockIdx.x * blockDim.x + threadIdx.x;
    int w = gt >> 5, lane = gt & 31;
    if (w >= NVn) return;
    int base = g_off_all[w], deg = g_deg_all[w];
    int sub = lane >> 3, li = lane & 7;
    float a0 = 0.f, a1 = 0.f, a2 = 0.f, ah = 0.f;
    float c0 = 0.f, c1 = 0.f;
#pragma unroll 4
    for (int j = sub; j < deg; j += 4) {
        int pk = g_csr_all[base + j];
        int s = pk & 0xFFFFF, t = pk >> 20;
        float xv = g_xpad[(size_t)s * 8 + li];
        ah += g_dinv_v[s] * xv;
        if (t == 0)      { a0 += xv; c0 += 1.f; }
        else if (t == 1) { a1 += xv; c1 += 1.f; }
        else             { a2 += xv; }
    }
#pragma unroll
    for (int o = 8; o < 32; o <<= 1) {
        a0 += __shfl_xor_sync(0xffffffffu, a0, o);
        a1 += __shfl_xor_sync(0xffffffffu, a1, o);
        a2 += __shfl_xor_sync(0xffffffffu, a2, o);
        ah += __shfl_xor_sync(0xffffffffu, ah, o);
        c0 += __shfl_xor_sync(0xffffffffu, c0, o);
        c1 += __shfl_xor_sync(0xffffffffu, c1, o);
    }
    if (sub == 0) {
        float dvd = g_dinv_v[w];
        float h1 = dvd * ah;
        float c2 = (float)deg - c0 - c1;
        if (li < 5) {
            float* zz = g_z + (size_t)w * ZW;
            zz[5 + li]  = a0 / fmaxf(c0, 1.f);
            zz[10 + li] = a1 / fmaxf(c1, 1.f);
            zz[15 + li] = a2 / fmaxf(c2, 1.f);
            zz[20 + li] = h1;
            if (li == 0) zz[35] = 0.f;
        }
        p1[(size_t)w * 8 + li] = dvd * h1;
    }
}

__global__ void k_hop8_gather(const float* __restrict__ pprev, float* __restrict__ pnext,
                              int k, int write_p) {
    int gt = blockIdx.x * blockDim.x + threadIdx.x;
    int w = gt >> 5, lane = gt & 31;
    if (w >= NVn) return;
    int base = g_off_all[w], deg = g_deg_all[w];
    int pair = lane >> 1, h = lane & 1;
    float4 a = make_float4(0.f, 0.f, 0.f, 0.f);
    for (int j = pair; j < deg; j += 16) {
        int s = g_csr_all[base + j] & 0xFFFFF;
        float4 v = ((const float4*)(pprev + (size_t)s * 8))[h];
        a.x += v.x; a.y += v.y; a.z += v.z; a.w += v.w;
    }
#pragma unroll
    for (int o = 2; o < 32; o <<= 1) {
        a.x += __shfl_xor_sync(0xffffffffu, a.x, o);
        a.y += __shfl_xor_sync(0xffffffffu, a.y, o);
        a.z += __shfl_xor_sync(0xffffffffu, a.z, o);
        a.w += __shfl_xor_sync(0xffffffffu, a.w, o);
    }
    if (lane < 2) {
        float dv = g_dinv_v[w];
        float4 hx = make_float4(dv * a.x, dv * a.y, dv * a.z, dv * a.w);
        float* zz = g_z + (size_t)w * ZW + 20 + k * 5;
        if (h == 0) { zz[0] = hx.x; zz[1] = hx.y; zz[2] = hx.z; zz[3] = hx.w; }
        else        { zz[4] = hx.x; }
        if (write_p)
            ((float4*)(pnext + (size_t)w * 8))[h] =
                make_float4(dv * hx.x, dv * hx.y, dv * hx.z, dv * hx.w);
    }
}

// --------- ei_h / ei_in z-gathers (one warp per node per graph) ------------
__global__ void k_gather_hin() {
    int gt = blockIdx.x * blockDim.x + threadIdx.x;
    int w2 = gt >> 5, lane = gt & 31;
    if (w2 >= 2 * NSn) return;
    int sub = lane >> 4, li = lane & 15;
    int isH = (w2 < NSn);
    int w = isH ? w2 : (w2 - NSn);

    if (isH) {
        int base = g_off_all[NVn + NSn + w], deg = g_deg_all[NVn + NSn + w];
        float4 aW = make_float4(0.f, 0.f, 0.f, 0.f);
        float4 aU = make_float4(0.f, 0.f, 0.f, 0.f);
        float wsum = 0.f;
        for (int j0 = 0; j0 < deg; j0 += 32) {
            int idx = j0 + lane;
            int sl = 0; float wl = 0.f;
            if (idx < deg) { sl = g_csr_all[base + idx]; wl = g_csrw[base + idx]; }
            wsum += wl;
            int mres = deg - j0; if (mres > 32) mres = 32;
#pragma unroll
            for (int jj = 0; jj < 16; jj++) {
                int e2 = 2 * jj + sub;
                int s = __shfl_sync(0xffffffffu, sl, e2);
                float wt = __shfl_sync(0xffffffffu, wl, e2);
                if (e2 < mres && li < 9) {
                    float4 t = ((const float4*)(g_z + (size_t)s * ZW))[li];
                    aU.x += t.x; aU.y += t.y; aU.z += t.z; aU.w += t.w;
                    aW.x += wt * t.x; aW.y += wt * t.y; aW.z += wt * t.z; aW.w += wt * t.w;
                }
            }
        }
        aU.x += __shfl_xor_sync(0xffffffffu, aU.x, 16);
        aU.y += __shfl_xor_sync(0xffffffffu, aU.y, 16);
        aU.z += __shfl_xor_sync(0xffffffffu, aU.z, 16);
        aU.w += __shfl_xor_sync(0xffffffffu, aU.w, 16);
        aW.x += __shfl_xor_sync(0xffffffffu, aW.x, 16);
        aW.y += __shfl_xor_sync(0xffffffffu, aW.y, 16);
        aW.z += __shfl_xor_sync(0xffffffffu, aW.z, 16);
        aW.w += __shfl_xor_sync(0xffffffffu, aW.w, 16);
#pragma unroll
        for (int o = 16; o; o >>= 1) wsum += __shfl_xor_sync(0xffffffffu, wsum, o);
        if (sub == 0 && li < 9) {
            ((float4*)(g_aggu + (size_t)w * 36))[li] = aU;
            ((float4*)(g_aggw + (size_t)w * 36))[li] = aW;
        }
        if (lane == 0) g_wsum[w] = wsum;
    } else {
        int base = g_off_all[NVn + 2 * NSn + w], deg = g_deg_all[NVn + 2 * NSn + w];
        float4 aU = make_float4(0.f, 0.f, 0.f, 0.f);
        for (int j0 = 0; j0 < deg; j0 += 32) {
            int idx = j0 + lane;
            int sl = (idx < deg) ? g_csr_all[base + idx] : 0;
            int mres = deg - j0; if (mres > 32) mres = 32;
#pragma unroll
            for (int jj = 0; jj < 16; jj++) {
                int e2 = 2 * jj + sub;
                int s = __shfl_sync(0xffffffffu, sl, e2);
                if (e2 < mres && li < 9) {
                    float4 t = ((const float4*)(g_z + (size_t)s * ZW))[li];
                    aU.x += t.x; aU.y += t.y; aU.z += t.z; aU.w += t.w;
                }
            }
        }
        aU.x += __shfl_xor_sync(0xffffffffu, aU.x, 16);
        aU.y += __shfl_xor_sync(0xffffffffu, aU.y, 16);
        aU.z += __shfl_xor_sync(0xffffffffu, aU.z, 16);
        aU.w += __shfl_xor_sync(0xffffffffu, aU.w, 16);
        if (sub == 0 && li < 9)
            ((float4*)(g_aggin + (size_t)w * 36))[li] = aU;
    }
}

// ---------------------- tiled GEMM building blocks -------------------------
__device__ __forceinline__ void stage_w(float* sW, const float* __restrict__ g, int n) {
    for (int e = threadIdx.x; e < n; e += 256) sW[e] = g[e];
}
__device__ __forceinline__ void stage_a64(float* sA, const float* __restrict__ g,
                                          int vbase, const float* sScale) {
    for (int e = threadIdx.x; e < 64 * 64; e += 256) {
        int n = e >> 6, j = e & 63;
        int v = vbase + n; if (v >= NSn) v = NSn - 1;
        float s = sScale ? sScale[n] : 1.f;
        sA[j * AST + n] = g[(size_t)v * 64 + j] * s;
    }
}
__device__ __forceinline__ void stage_a36(float* sA, const float* __restrict__ g,
                                          int vbase, const float* sScale) {
    for (int e = threadIdx.x; e < 64 * 36; e += 256) {
        int n = e / 36, j = e - n * 36;
        int v = vbase + n; if (v >= NSn) v = NSn - 1;
        float s = sScale ? sScale[n] : 1.f;
        sA[j * AST + n] = g[(size_t)v * 36 + j] * s;
    }
}
__device__ __forceinline__ void gemm16(const float* __restrict__ sW, const float* __restrict__ sA,
                                       int J, int c4, int n0, float acc[4][4]) {
#pragma unroll 4
    for (int j = 0; j < J; j++) {
        float4 wv = *(const float4*)(sW + j * 64 + c4);
        float4 av = *(const float4*)(sA + j * AST + n0);
        acc[0][0] += av.x * wv.x; acc[0][1] += av.x * wv.y; acc[0][2] += av.x * wv.z; acc[0][3] += av.x * wv.w;
        acc[1][0] += av.y * wv.x; acc[1][1] += av.y * wv.y; acc[1][2] += av.y * wv.z; acc[1][3] += av.y * wv.w;
        acc[2][0] += av.z * wv.x; acc[2][1] += av.z * wv.y; acc[2][2] += av.z * wv.z; acc[2][3] += av.z * wv.w;
        acc[3][0] += av.w * wv.x; acc[3][1] += av.w * wv.y; acc[3][2] += av.w * wv.z; acc[3][3] += av.w * wv.w;
    }
}

// --------------------- state dense chain (layers 2-5) ----------------------
__global__ void __launch_bounds__(256) k_state_dense(
        const float* __restrict__ state_x, const float* __restrict__ W3_root,
        const float* __restrict__ b3, const float* __restrict__ W32_r,
        const float* __restrict__ b32, const float* __restrict__ W4_r,
        const float* __restrict__ b4, const float* __restrict__ W42_r,
        const float* __restrict__ b42) {
    __shared__ float sW[64 * 64];
    __shared__ float sA[64 * AST];
    __shared__ float sInvH[64], sInvI[64], sWsum[64], sPosH[64], sPosI[64], sDin[64];
    int tid = threadIdx.x;
    int vbase = blockIdx.x * 64;
    if (tid < 64) {
        int v = vbase + tid; if (v >= NSn) v = NSn - 1;
        float ch = (float)g_deg_all[NVn + NSn + v];
        float ci = (float)g_deg_all[NVn + 2 * NSn + v];
        sInvH[tid] = 1.f / fmaxf(ch, 1.f);
        sInvI[tid] = 1.f / fmaxf(ci, 1.f);
        sPosH[tid] = (ch > 0.f) ? 1.f : 0.f;
        sPosI[tid] = (ci > 0.f) ? 1.f : 0.f;
        sWsum[tid] = g_wsum[v];
        sDin[tid]  = g_dinv_s[v];
    }
    __syncthreads();
    int c4 = (tid & 15) * 4, n0 = (tid >> 4) * 4;
    float acc[4][4];
    float4 bv, cv;

    // ---- L2: graph_conv ----
    stage_a36(sA, g_aggw, vbase, nullptr);
    stage_w(sW, g_WzW[0], 35 * 64);
    __syncthreads();
    bv = *(const float4*)(b3 + c4);
    cv = *(const float4*)(g_c0W[0] + c4);
#pragma unroll
    for (int i = 0; i < 4; i++) {
        float ws = sWsum[n0 + i];
        acc[i][0] = bv.x + ws * cv.x; acc[i][1] = bv.y + ws * cv.y;
        acc[i][2] = bv.z + ws * cv.z; acc[i][3] = bv.w + ws * cv.w;
    }
    gemm16(sW, sA, 35, c4, n0, acc);
    __syncthreads();
    for (int e = tid; e < 64 * 5; e += 256) {
        int n = e / 5, j = e - n * 5;
        int v = vbase + n; if (v >= NSn) v = NSn - 1;
        sA[j * AST + n] = state_x[(size_t)v * 5 + j];
    }
    stage_w(sW, W3_root, 5 * 64);
    __syncthreads();
    gemm16(sW, sA, 5, c4, n0, acc);
#pragma unroll
    for (int i = 0; i < 4; i++) {
        int v = vbase + n0 + i;
        if (v < NSn) {
            float4 o = make_float4(fmaxf(acc[i][0], 0.f), fmaxf(acc[i][1], 0.f),
                                   fmaxf(acc[i][2], 0.f), fmaxf(acc[i][3], 0.f));
            *(float4*)(g_ta + (size_t)v * 64 + c4) = o;
        }
    }
    __syncthreads();

    // ---- L3: conv32 ----
    stage_a36(sA, g_aggu, vbase, sInvH);
    stage_w(sW, g_WzW[1], 35 * 64);
    __syncthreads();
    bv = *(const float4*)(b32 + c4);
    cv = *(const float4*)(g_c0W[1] + c4);
#pragma unroll
    for (int i = 0; i < 4; i++) {
        float p = sPosH[n0 + i];
        acc[i][0] = bv.x + p * cv.x; acc[i][1] = bv.y + p * cv.y;
        acc[i][2] = bv.z + p * cv.z; acc[i][3] = bv.w + p * cv.w;
    }
    gemm16(sW, sA, 35, c4, n0, acc);
    __syncthreads();
    stage_a64(sA, g_ta, vbase, nullptr);
    stage_w(sW, W32_r, 64 * 64);
    __syncthreads();
    gemm16(sW, sA, 64, c4, n0, acc);
#pragma unroll
    for (int i = 0; i < 4; i++) {
        int v = vbase + n0 + i;
        if (v < NSn) {
            float4 o = make_float4(fmaxf(acc[i][0], 0.f), fmaxf(acc[i][1], 0.f),
                                   fmaxf(acc[i][2], 0.f), fmaxf(acc[i][3], 0.f));
            *(float4*)(g_tb + (size_t)v * 64 + c4) = o;
        }
    }
    __syncthreads();

    // ---- L4: conv4 ----
    stage_a36(sA, g_aggin, vbase, sInvI);
    stage_w(sW, g_WzW[2], 35 * 64);
    __syncthreads();
    bv = *(const float4*)(b4 + c4);
    cv = *(const float4*)(g_c0W[2] + c4);
#pragma unroll
    for (int i = 0; i < 4; i++) {
        float p = sPosI[n0 + i];
        acc[i][0] = bv.x + p * cv.x; acc[i][1] = bv.y + p * cv.y;
        acc[i][2] = bv.z + p * cv.z; acc[i][3] = bv.w + p * cv.w;
    }
    gemm16(sW, sA, 35, c4, n0, acc);
    __syncthreads();
    stage_a64(sA, g_tb, vbase, nullptr);
    stage_w(sW, W4_r, 64 * 64);
    __syncthreads();
    gemm16(sW, sA, 64, c4, n0, acc);
#pragma unroll
    for (int i = 0; i < 4; i++) {
        int v = vbase + n0 + i;
        if (v < NSn) {
            float4 o = make_float4(fmaxf(acc[i][0], 0.f), fmaxf(acc[i][1], 0.f),
                                   fmaxf(acc[i][2], 0.f), fmaxf(acc[i][3], 0.f));
            *(float4*)(g_ta + (size_t)v * 64 + c4) = o;
        }
    }
    __syncthreads();

    // ---- L5: conv42 -> sx5, pin ----
    stage_a36(sA, g_aggin, vbase, sInvI);
    stage_w(sW, g_WzW[3], 35 * 64);
    __syncthreads();
    bv = *(const float4*)(b42 + c4);
    cv = *(const float4*)(g_c0W[3] + c4);
#pragma unroll
    for (int i = 0; i < 4; i++) {
        float p = sPosI[n0 + i];
        acc[i][0] = bv.x + p * cv.x; acc[i][1] = bv.y + p * cv.y;
        acc[i][2] = bv.z + p * cv.z; acc[i][3] = bv.w + p * cv.w;
    }
    gemm16(sW, sA, 35, c4, n0, acc);
    __syncthreads();
    stage_a64(sA, g_ta, vbase, nullptr);
    stage_w(sW, W42_r, 64 * 64);
    __syncthreads();
    gemm16(sW, sA, 64, c4, n0, acc);
#pragma unroll
    for (int i = 0; i < 4; i++) {
        int v = vbase + n0 + i;
        if (v < NSn) {
            float dv = sDin[n0 + i];
            float4 o = make_float4(fmaxf(acc[i][0], 0.f), fmaxf(acc[i][1], 0.f),
                                   fmaxf(acc[i][2], 0.f), fmaxf(acc[i][3], 0.f));
            *(float4*)(g_sx5 + (size_t)v * 64 + c4) = o;
            *(float4*)(g_pin + (size_t)v * 64 + c4) =
                make_float4(dv * o.x, dv * o.y, dv * o.z, dv * o.w);
        }
    }
}

// TAG-state hop, p-form.
__global__ void k_hop64p(const float* __restrict__ pprev, float* __restrict__ pnext) {
    int gt = blockIdx.x * blockDim.x + threadIdx.x;
    int w = gt >> 5, lane = gt & 31;
    if (w >= NSn) return;
    int base = g_off_all[NVn + w], deg = g_deg_all[NVn + w];
    int sub = lane >> 4, li = lane & 15;
    float4 a = make_float4(0.f, 0.f, 0.f, 0.f);
    for (int j0 = 0; j0 < deg; j0 += 32) {
        int idx = j0 + lane;
        int sl = (idx < deg) ? g_csr_all[base + idx] : 0;
        int mres = deg - j0; if (mres > 32) mres = 32;
#pragma unroll
        for (int jj = 0; jj < 16; jj++) {
            int e2 = 2 * jj + sub;
            int s = __shfl_sync(0xffffffffu, sl, e2);
            if (e2 < mres) {
                float4 v = ((const float4*)(pprev + (size_t)s * 64))[li];
                a.x += v.x; a.y += v.y; a.z += v.z; a.w += v.w;
            }
        }
    }
    a.x += __shfl_xor_sync(0xffffffffu, a.x, 16);
    a.y += __shfl_xor_sync(0xffffffffu, a.y, 16);
    a.z += __shfl_xor_sync(0xffffffffu, a.z, 16);
    a.w += __shfl_xor_sync(0xffffffffu, a.w, 16);
    if (sub == 0) {
        float dv = g_dinv_s[w];
        float dv2 = dv * dv;
        ((float4*)(pnext + (size_t)w * 64))[li] =
            make_float4(dv2 * a.x, dv2 * a.y, dv2 * a.z, dv2 * a.w);
    }
}

// conv5 sum gather over ei_ss.
__global__ void k_sum64_gather(const float* __restrict__ feat, float* __restrict__ acc) {
    int gt = blockIdx.x * blockDim.x + threadIdx.x;
    int w = gt >> 5, lane = gt & 31;
    if (w >= NSn) return;
    int base = g_off_all[NVn + w], deg = g_deg_all[NVn + w];
    int sub = lane >> 4, li = lane & 15;
    float4 a = make_float4(0.f, 0.f, 0.f, 0.f);
    for (int j0 = 0; j0 < deg; j0 += 32) {
        int idx = j0 + lane;
        int sl = (idx < deg) ? g_csr_all[base + idx] : 0;
        int mres = deg - j0; if (mres > 32) mres = 32;
#pragma unroll
        for (int jj = 0; jj < 16; jj++) {
            int e2 = 2 * jj + sub;
            int s = __shfl_sync(0xffffffffu, sl, e2);
            if (e2 < mres) {
                float4 v = ((const float4*)(feat + (size_t)s * 64))[li];
                a.x += v.x; a.y += v.y; a.z += v.z; a.w += v.w;
            }
        }
    }
    a.x += __shfl_xor_sync(0xffffffffu, a.x, 16);
    a.y += __shfl_xor_sync(0xffffffffu, a.y, 16);
    a.z += __shfl_xor_sync(0xffffffffu, a.z, 16);
    a.w += __shfl_xor_sync(0xffffffffu, a.w, 16);
    if (sub == 0)
        ((float4*)(acc + (size_t)w * 64))[li] = a;
}

// TAG output dense: sx6 = relu(b2 + sx5@W2_0 + sum_k (sqd*pk_k)@W2_{k+1})
__global__ void __launch_bounds__(256) k_tag_dense(
        const float* __restrict__ W2, const float* __restrict__ b2) {
    __shared__ float sW[64 * 64];
    __shared__ float sA[64 * AST];
    __shared__ float sSq[64];
    int tid = threadIdx.x;
    int vbase = blockIdx.x * 64;
    if (tid < 64) {
        int v = vbase + tid; if (v >= NSn) v = NSn - 1;
        sSq[tid] = g_sqd_s[v];
    }
    __syncthreads();
    int c4 = (tid & 15) * 4, n0 = (tid >> 4) * 4;
    float acc[4][4];
    float4 bv;

    stage_a64(sA, g_sx5, vbase, nullptr);
    stage_w(sW, W2, 64 * 64);
    __syncthreads();
    bv = *(const float4*)(b2 + c4);
#pragma unroll
    for (int i = 0; i < 4; i++) {
        acc[i][0] = bv.x; acc[i][1] = bv.y; acc[i][2] = bv.z; acc[i][3] = bv.w;
    }
    gemm16(sW, sA, 64, c4, n0, acc);
    __syncthreads();
#pragma unroll
    for (int k = 0; k < 3; k++) {
        stage_a64(sA, g_pk[k], vbase, sSq);
        stage_w(sW, W2 + (size_t)(k + 1) * 4096, 64 * 64);
        __syncthreads();
        gemm16(sW, sA, 64, c4, n0, acc);
        __syncthreads();
    }
#pragma unroll
    for (int i = 0; i < 4; i++) {
        int v = vbase + n0 + i;
        if (v < NSn) {
            float4 o = make_float4(fmaxf(acc[i][0], 0.f), fmaxf(acc[i][1], 0.f),
                                   fmaxf(acc[i][2], 0.f), fmaxf(acc[i][3], 0.f));
            *(float4*)(g_sx6 + (size_t)v * 64 + c4) = o;
        }
    }
}

// conv5 dense + head.
__global__ void __launch_bounds__(256) k_conv5_head(
        const float* __restrict__ W5_l, const float* __restrict__ W5_r,
        const float* __restrict__ b5, const float* __restrict__ Wl,
        const float* __restrict__ bl, float* __restrict__ out) {
    __shared__ float sW[64 * 64];
    __shared__ float sA[64 * AST];
    __shared__ float sInv[64];
    int tid = threadIdx.x;
    int vbase = blockIdx.x * 64;
    if (tid < 64) {
        int v = vbase + tid; if (v >= NSn) v = NSn - 1;
        sInv[tid] = 1.f / fmaxf(g_cntf_s[v], 1.f);
    }
    __syncthreads();
    int c4 = (tid & 15) * 4, n0 = (tid >> 4) * 4;
    float acc[4][4];
    float4 bv;

    stage_a64(sA, g_accs5, vbase, sInv);
    stage_w(sW, W5_l, 64 * 64);
    __syncthreads();
    bv = *(const float4*)(b5 + c4);
#pragma unroll
    for (int i = 0; i < 4; i++) {
        acc[i][0] = bv.x; acc[i][1] = bv.y; acc[i][2] = bv.z; acc[i][3] = bv.w;
    }
    gemm16(sW, sA, 64, c4, n0, acc);
    __syncthreads();
    stage_a64(sA, g_sx6, vbase, nullptr);
    stage_w(sW, W5_r, 64 * 64);
    __syncthreads();
    gemm16(sW, sA, 64, c4, n0, acc);
    __syncthreads();
#pragma unroll
    for (int i = 0; i < 4; i++) {
#pragma unroll
        for (int k = 0; k < 4; k++)
            sA[(c4 + k) * AST + n0 + i] = fmaxf(acc[i][k], 0.f);
    }
    stage_w(sW, Wl, 64 * 8);
    __syncthreads();
#pragma unroll
    for (int u = 0; u < 2; u++) {
        int idx = tid * 2 + u;
        int n = idx >> 3, o = idx & 7;
        float s = bl[o];
#pragma unroll 8
        for (int j = 0; j < 64; j++) s += sA[j * AST + n] * sW[j * 8 + o];
        int v = vbase + n;
        if (v < NSn) out[(size_t)v * 8 + o] = s;
    }
}

// ------------------------------- launch ------------------------------------

extern "C" void kernel_launch(void* const* d_in, const int* in_sizes, int n_in,
                              void* d_out, int out_size) {
    const float* game_x  = (const float*)d_in[0];
    const float* state_x = (const float*)d_in[1];
    const int*   ei_vv   = (const int*)d_in[2];
    const int*   et_vv   = (const int*)d_in[3];
    const int*   ei_h    = (const int*)d_in[4];
    const float* ew_h    = (const float*)d_in[5];
    const int*   ei_in   = (const int*)d_in[6];
    const int*   ei_ss   = (const int*)d_in[7];
    const float* W1_rel  = (const float*)d_in[8];
    const float* W1_root = (const float*)d_in[9];
    const float* b1      = (const float*)d_in[10];
    const float* W12     = (const float*)d_in[11];
    const float* b12     = (const float*)d_in[12];
    const float* W2      = (const float*)d_in[13];
    const float* b2      = (const float*)d_in[14];
    const float* W3_rel  = (const float*)d_in[15];
    const float* W3_root = (const float*)d_in[16];
    const float* b3      = (const float*)d_in[17];
    const float* W32_l   = (const float*)d_in[18];
    const float* W32_r   = (const float*)d_in[19];
    const float* b32     = (const float*)d_in[20];
    const float* W4_l    = (const float*)d_in[21];
    const float* W4_r    = (const float*)d_in[22];
    const float* b4      = (const float*)d_in[23];
    const float* W42_l   = (const float*)d_in[24];
    const float* W42_r   = (const float*)d_in[25];
    const float* b42     = (const float*)d_in[26];
    const float* W5_l    = (const float*)d_in[27];
    const float* W5_r    = (const float*)d_in[28];
    const float* b5      = (const float*)d_in[29];
    const float* Wl      = (const float*)d_in[30];
    const float* bl      = (const float*)d_in[31];
    float* out = (float*)d_out;

    int Evv = in_sizes[2] / 2;
    int Eh  = in_sizes[4] / 2;
    int Ein = in_sizes[6] / 2;
    int Ess = in_sizes[7] / 2;
    int Etot = Evv + Ess + Eh + Ein;

    int* pi_deg;
    float *p_pv, *p_pin, *p_pk, *p_sx6, *p_accs5;
    cudaGetSymbolAddress((void**)&pi_deg,  g_deg_all);
    cudaGetSymbolAddress((void**)&p_pv,    g_pv);
    cudaGetSymbolAddress((void**)&p_pin,   g_pin);
    cudaGetSymbolAddress((void**)&p_pk,    g_pk);
    cudaGetSymbolAddress((void**)&p_sx6,   g_sx6);
    cudaGetSymbolAddress((void**)&p_accs5, g_accs5);

    float* p_pv0 = p_pv;
    float* p_pv1 = p_pv + (size_t)NVn * 8;
    float* p_pk0 = p_pk;
    float* p_pk1 = p_pk + (size_t)NSn * 64;
    float* p_pk2 = p_pk1 + (size_t)NSn * 64;

    const int T = 256;
    auto nb = [](long n, int t) { return (int)((n + t - 1) / t); };
    int nbv_warp = nb((long)NVn * 32, T);
    int nbs_warp = nb((long)NSn * 32, T);
    int ndense = nb(NSn, 64);

    // 0) zero unified degree array
    cudaMemsetAsync(pi_deg, 0, (size_t)NDEG * 4, 0);

    // 1) fused count + pad + weight prep, then scan, then fill
    k_count_pad_prep<<<nb(Etot, T), T>>>(ei_vv, ei_ss, ei_h, ei_in,
                                         Evv, Ess, Eh, Ein,
                                         game_x, W1_rel, W1_root, b1, W12, b12,
                                         W3_rel, W32_l, W4_l, W42_l);
    k_scan<<<nb(NDEG, 1024), 1024>>>(NDEG);
    k_fill_all<<<nb(Etot, T), T>>>(ei_vv, et_vv, ei_ss, ei_h, ew_h, ei_in,
                                   Evv, Ess, Eh, Ein);

    // 2) game graph -> z
    k_rgcn_hop1<<<nbv_warp, T>>>(p_pv0);
    k_hop8_gather<<<nbv_warp, T>>>(p_pv0, p_pv1, 1, 1);
    k_hop8_gather<<<nbv_warp, T>>>(p_pv1, p_pv0, 2, 0);

    // 3) ei_h + ei_in gathers (split), then state dense chain
    k_gather_hin<<<nb((long)2 * NSn * 32, T), T>>>();
    k_state_dense<<<ndense, 256>>>(state_x, W3_root, b3, W32_r, b32,
                                   W4_r, b4, W42_r, b42);

    // 4) TAG-state hops + dense output
    k_hop64p<<<nbs_warp, T>>>(p_pin, p_pk0);
    k_hop64p<<<nbs_warp, T>>>(p_pk0, p_pk1);
    k_hop64p<<<nbs_warp, T>>>(p_pk1, p_pk2);
    k_tag_dense<<<ndense, 256>>>(W2, b2);

    // 5) conv5 gather + dense + head
    k_sum64_gather<<<nbs_warp, T>>>(p_sx6, p_accs5);
    k_conv5_head<<<ndense, 256>>>(W5_l, W5_r, b5, Wl, bl, out);
}